// round 5
// baseline (speedup 1.0000x reference)
#include <cuda_runtime.h>

#define FULLMASK 0xFFFFFFFFu

namespace {
constexpr int N_SEQ = 4096;
constexpr int T = 128;
constexpr float NEG_HALF_LOG2PI = -0.91893853320467274f;
}

__device__ float g_enc[(size_t)N_SEQ * T * 8];
__device__ float g_th[(size_t)N_SEQ * T * 32];
__device__ float g_logp[(size_t)N_SEQ * T];

typedef unsigned long long u64;

__device__ __forceinline__ u64 pack2(float lo, float hi)
{
    u64 r;
    asm("mov.b64 %0, {%1, %2};" : "=l"(r) : "f"(lo), "f"(hi));
    return r;
}
__device__ __forceinline__ void unpack2(u64 v, float& lo, float& hi)
{
    asm("mov.b64 {%0, %1}, %2;" : "=f"(lo), "=f"(hi) : "l"(v));
}
__device__ __forceinline__ u64 fma2(u64 a, u64 b, u64 c)
{
    u64 d;
    asm("fma.rn.f32x2 %0, %1, %2, %3;" : "=l"(d) : "l"(a), "l"(b), "l"(c));
    return d;
}
__device__ __forceinline__ u64 mul2(u64 a, u64 b)
{
    u64 d;
    asm("mul.rn.f32x2 %0, %1, %2;" : "=l"(d) : "l"(a), "l"(b));
    return d;
}

// ---------------- encoder: g_enc[n][t][d] = tanh(relu(x*w1+b1) @ w2 + b2)
__global__ void enc_kernel(const float* __restrict__ x,
                           const float* __restrict__ e1w, const float* __restrict__ e1b,
                           const float* __restrict__ e2w, const float* __restrict__ e2b)
{
    __shared__ float s1w[64], s1b[64], s2w[64 * 8], s2b[8];
    int tid = threadIdx.x;
    if (tid < 64) { s1w[tid] = e1w[tid]; s1b[tid] = e1b[tid]; }
    if (tid < 8) s2b[tid] = e2b[tid];
    for (int i = tid; i < 64 * 8; i += blockDim.x) s2w[i] = e2w[i];
    __syncthreads();
    int idx = blockIdx.x * blockDim.x + tid;
    if (idx >= N_SEQ * T) return;
    float xv = x[idx];
    float acc[8];
#pragma unroll
    for (int d = 0; d < 8; d++) acc[d] = s2b[d];
#pragma unroll 8
    for (int h = 0; h < 64; h++) {
        float e = fmaxf(fmaf(xv, s1w[h], s1b[h]), 0.f);
#pragma unroll
        for (int d = 0; d < 8; d++) acc[d] = fmaf(e, s2w[h * 8 + d], acc[d]);
    }
    float4 o0 = make_float4(tanhf(acc[0]), tanhf(acc[1]), tanhf(acc[2]), tanhf(acc[3]));
    float4 o1 = make_float4(tanhf(acc[4]), tanhf(acc[5]), tanhf(acc[6]), tanhf(acc[7]));
    float4* op = reinterpret_cast<float4*>(g_enc + (size_t)idx * 8);
    op[0] = o0;
    op[1] = o1;
}

// ---------------- recurrence: warp pair shares 2 sequences, splits i in half.
// No shuffles; tmp staged in WARP-PRIVATE smem (duplicated (v,v) u64), partials
// exchanged through double-buffered `part` with ONE __syncthreads per step.
// Block = 256 threads = 8 warps = 4 pairs = 8 sequences. Grid = 512.
__global__ void __launch_bounds__(256) rec_kernel(const float* __restrict__ A,
                                                  const float* __restrict__ initw)
{
    __shared__ ulonglong2 A4[2048];          // [(i*2+q)*32 + L]: d pairs
    __shared__ float part[2][8][2][32];      // [par][warpInBlock][seq][lane]
    __shared__ u64 tmpz[2][8][2][32];        // [par][warpInBlock][seq][i] (warp-private)

    int tid = threadIdx.x;
    for (int idx = tid; idx < 2048; idx += 256) {
        int i = idx >> 6, q = (idx >> 5) & 1, L = idx & 31;
        const float* base = A + i * 256 + q * 128 + L;
        ulonglong2 v;
        v.x = pack2(base[0], base[32]);
        v.y = pack2(base[64], base[96]);
        A4[idx] = v;
    }

    int wib = tid >> 5;        // 0..7
    int pairIB = wib >> 1;     // 0..3
    int half = wib & 1;        // which i half / owned seq
    int L = tid & 31;
    int n0 = (blockIdx.x * 4 + pairIB) * 2;

    float init = initw[L];

    // initial staging (parity 0, read at t=1): both seqs, own private copy
    tmpz[0][wib][0][L] = pack2(init, init);
    tmpz[0][wib][1][L] = pack2(init, init);
    // t=0 tanh store for owned seq
    g_th[((size_t)(n0 + half) * T) * 32 + L] = tanhf(init);
    __syncthreads();

    const float4* ep0 = reinterpret_cast<const float4*>(g_enc + (size_t)n0 * T * 8);
    const float4* ep1 = reinterpret_cast<const float4*>(g_enc + (size_t)(n0 + 1) * T * 8);

    int iBase = half * 16;
    int w0 = pairIB * 2;

#pragma unroll 1
    for (int t = 1; t < T; t++) {
        int parR = (t - 1) & 1;
        int parW = t & 1;

        u64 B0[4], B1[4];
#pragma unroll
        for (int k = 0; k < 4; k++) { B0[k] = 0ull; B1[k] = 0ull; }

#pragma unroll 8
        for (int ii = 0; ii < 16; ii++) {
            int i = iBase + ii;
            ulonglong2 a0 = A4[(i * 2 + 0) * 32 + L];
            ulonglong2 a1 = A4[(i * 2 + 1) * 32 + L];
            u64 v0 = tmpz[parR][wib][0][i];
            u64 v1 = tmpz[parR][wib][1][i];
            B0[0] = fma2(v0, a0.x, B0[0]);
            B0[1] = fma2(v0, a0.y, B0[1]);
            B0[2] = fma2(v0, a1.x, B0[2]);
            B0[3] = fma2(v0, a1.y, B0[3]);
            B1[0] = fma2(v1, a0.x, B1[0]);
            B1[1] = fma2(v1, a0.y, B1[1]);
            B1[2] = fma2(v1, a1.x, B1[2]);
            B1[3] = fma2(v1, a1.y, B1[3]);
        }

        {
            float4 e0 = ep0[(t - 1) * 2];
            float4 e1 = ep0[(t - 1) * 2 + 1];
            u64 acc = mul2(pack2(e0.x, e0.y), B0[0]);
            acc = fma2(pack2(e0.z, e0.w), B0[1], acc);
            acc = fma2(pack2(e1.x, e1.y), B0[2], acc);
            acc = fma2(pack2(e1.z, e1.w), B0[3], acc);
            float lo, hi;
            unpack2(acc, lo, hi);
            part[parW][wib][0][L] = lo + hi;
        }
        {
            float4 e0 = ep1[(t - 1) * 2];
            float4 e1 = ep1[(t - 1) * 2 + 1];
            u64 acc = mul2(pack2(e0.x, e0.y), B1[0]);
            acc = fma2(pack2(e0.z, e0.w), B1[1], acc);
            acc = fma2(pack2(e1.x, e1.y), B1[2], acc);
            acc = fma2(pack2(e1.z, e1.w), B1[3], acc);
            float lo, hi;
            unpack2(acc, lo, hi);
            part[parW][wib][1][L] = lo + hi;
        }

        __syncthreads();

        // combine partials (redundantly per warp) into warp-private staging
#pragma unroll
        for (int s = 0; s < 2; s++) {
            float v = part[parW][w0][s][L] + part[parW][w0 + 1][s][L];
            tmpz[parW][wib][s][L] = pack2(v, v);
            if (s == half)
                g_th[((size_t)(n0 + s) * T + t) * 32 + L] = tanhf(v);
        }
        __syncwarp();
    }
}

// ---------------- phi: one thread per (n,t) item; weights broadcast from smem;
// hidden activations fully register-resident (R3 configuration).
__global__ void __launch_bounds__(256) phi_kernel(
    const float* __restrict__ x,
    const float* __restrict__ w1, const float* __restrict__ b1,
    const float* __restrict__ w2, const float* __restrict__ b2,
    const float* __restrict__ muw, const float* __restrict__ mub,
    const float* __restrict__ sgw, const float* __restrict__ sgb,
    const float* __restrict__ alw, const float* __restrict__ alb)
{
    __shared__ float sm[8352];
    int tid = threadIdx.x;

    for (int i = tid; i < 2048; i += 256) sm[i] = w1[i];
    for (int i = tid; i < 4096; i += 256) sm[2048 + i] = w2[i];
    for (int i = tid; i < 2048; i += 256) {
        int k = i >> 5, c = i & 31;
        float v = 0.f;
        if (c < 10) v = muw[k * 10 + c];
        else if (c < 20) v = sgw[k * 10 + (c - 10)];
        else if (c < 30) v = alw[k * 10 + (c - 20)];
        sm[6144 + i] = v;
    }
    if (tid < 64) { sm[8192 + tid] = b1[tid]; sm[8256 + tid] = b2[tid]; }
    if (tid < 32) {
        float v = 0.f;
        if (tid < 10) v = mub[tid];
        else if (tid < 20) v = sgb[tid - 10];
        else if (tid < 30) v = alb[tid - 20];
        sm[8320 + tid] = v;
    }
    __syncthreads();

    const ulonglong2* w1v = reinterpret_cast<const ulonglong2*>(sm);
    const ulonglong2* w2v = reinterpret_cast<const ulonglong2*>(sm + 2048);
    const ulonglong2* whv = reinterpret_cast<const ulonglong2*>(sm + 6144);
    const u64* b1u = reinterpret_cast<const u64*>(sm + 8192);
    const u64* b2u = reinterpret_cast<const u64*>(sm + 8256);
    const u64* hbu = reinterpret_cast<const u64*>(sm + 8320);

    int item = blockIdx.x * 256 + tid;
    const float4* thp = reinterpret_cast<const float4*>(g_th + (size_t)item * 32);

    // ---- layer 1: h1[64] = relu(W1^T th + b1)
    u64 hp[32];
#pragma unroll
    for (int p = 0; p < 32; p++) hp[p] = b1u[p];

#pragma unroll
    for (int g = 0; g < 8; g++) {
        float4 v4 = thp[g];
        u64 vv0 = pack2(v4.x, v4.x), vv1 = pack2(v4.y, v4.y);
        u64 vv2 = pack2(v4.z, v4.z), vv3 = pack2(v4.w, v4.w);
#pragma unroll
        for (int q = 0; q < 16; q++) {
            ulonglong2 wA = w1v[(g * 4 + 0) * 16 + q];
            hp[2 * q]     = fma2(vv0, wA.x, hp[2 * q]);
            hp[2 * q + 1] = fma2(vv0, wA.y, hp[2 * q + 1]);
            ulonglong2 wB = w1v[(g * 4 + 1) * 16 + q];
            hp[2 * q]     = fma2(vv1, wB.x, hp[2 * q]);
            hp[2 * q + 1] = fma2(vv1, wB.y, hp[2 * q + 1]);
            ulonglong2 wC = w1v[(g * 4 + 2) * 16 + q];
            hp[2 * q]     = fma2(vv2, wC.x, hp[2 * q]);
            hp[2 * q + 1] = fma2(vv2, wC.y, hp[2 * q + 1]);
            ulonglong2 wD = w1v[(g * 4 + 3) * 16 + q];
            hp[2 * q]     = fma2(vv3, wD.x, hp[2 * q]);
            hp[2 * q + 1] = fma2(vv3, wD.y, hp[2 * q + 1]);
        }
    }
    float h1f[64];
#pragma unroll
    for (int p = 0; p < 32; p++) unpack2(hp[p], h1f[2 * p], h1f[2 * p + 1]);

    // ---- layer 2: h2[64] = relu(W2^T relu(h1) + b2)
    u64 h2[32];
#pragma unroll
    for (int p = 0; p < 32; p++) h2[p] = b2u[p];
#pragma unroll
    for (int i = 0; i < 64; i++) {
        float r = fmaxf(h1f[i], 0.f);
        u64 vv = pack2(r, r);
#pragma unroll
        for (int q = 0; q < 16; q++) {
            ulonglong2 w = w2v[i * 16 + q];
            h2[2 * q]     = fma2(vv, w.x, h2[2 * q]);
            h2[2 * q + 1] = fma2(vv, w.y, h2[2 * q + 1]);
        }
    }
    float h2f[64];
#pragma unroll
    for (int p = 0; p < 32; p++) unpack2(h2[p], h2f[2 * p], h2f[2 * p + 1]);

    // ---- heads
    u64 op[16];
#pragma unroll
    for (int p = 0; p < 16; p++) op[p] = hbu[p];
#pragma unroll
    for (int k = 0; k < 64; k++) {
        float r = fmaxf(h2f[k], 0.f);
        u64 vv = pack2(r, r);
#pragma unroll
        for (int q = 0; q < 8; q++) {
            ulonglong2 w = whv[k * 8 + q];
            op[2 * q]     = fma2(vv, w.x, op[2 * q]);
            op[2 * q + 1] = fma2(vv, w.y, op[2 * q + 1]);
        }
    }

    float o[32];
#pragma unroll
    for (int p = 0; p < 16; p++) unpack2(op[p], o[2 * p], o[2 * p + 1]);

    float xv = x[item];
    float amax = o[20];
#pragma unroll
    for (int k = 1; k < 10; k++) amax = fmaxf(amax, o[20 + k]);
    float asum = 0.f;
#pragma unroll
    for (int k = 0; k < 10; k++) asum += __expf(o[20 + k] - amax);
    float lc = amax + __logf(asum);

    float comp[10];
    float cmax = -1e30f;
#pragma unroll
    for (int k = 0; k < 10; k++) {
        float ls = o[10 + k];
        float z = (xv - o[k]) * __expf(-ls);
        comp[k] = o[20 + k] - lc - ls + NEG_HALF_LOG2PI - 0.5f * z * z;
        cmax = fmaxf(cmax, comp[k]);
    }
    float csum = 0.f;
#pragma unroll
    for (int k = 0; k < 10; k++) csum += __expf(comp[k] - cmax);
    g_logp[item] = cmax + __logf(csum);
}

// ---------------- reduce: out[n] = exp(sum_t logp[n,t]); warp per n
__global__ void __launch_bounds__(256) red_kernel(float* __restrict__ out)
{
    int wid = threadIdx.x >> 5;
    int L = threadIdx.x & 31;
    int n = blockIdx.x * 8 + wid;
    const float* lp = g_logp + (size_t)n * T;
    float s = lp[L] + lp[L + 32] + lp[L + 64] + lp[L + 96];
#pragma unroll
    for (int o = 16; o > 0; o >>= 1) s += __shfl_xor_sync(FULLMASK, s, o);
    if (L == 0) out[n] = __expf(s);
}

extern "C" void kernel_launch(void* const* d_in, const int* in_sizes, int n_in,
                              void* d_out, int out_size)
{
    (void)in_sizes; (void)n_in; (void)out_size;
    const float* x   = (const float*)d_in[0];
    const float* e1w = (const float*)d_in[1];
    const float* e1b = (const float*)d_in[2];
    const float* e2w = (const float*)d_in[3];
    const float* e2b = (const float*)d_in[4];
    const float* A   = (const float*)d_in[5];
    const float* iw  = (const float*)d_in[6];
    const float* w1  = (const float*)d_in[7];
    const float* b1  = (const float*)d_in[8];
    const float* w2  = (const float*)d_in[9];
    const float* b2  = (const float*)d_in[10];
    const float* muw = (const float*)d_in[11];
    const float* mub = (const float*)d_in[12];
    const float* sgw = (const float*)d_in[13];
    const float* sgb = (const float*)d_in[14];
    const float* alw = (const float*)d_in[15];
    const float* alb = (const float*)d_in[16];
    float* out = (float*)d_out;

    enc_kernel<<<(N_SEQ * T + 255) / 256, 256>>>(x, e1w, e1b, e2w, e2b);
    rec_kernel<<<512, 256>>>(A, iw);
    phi_kernel<<<(N_SEQ * T) / 256, 256>>>(
        x, w1, b1, w2, b2, muw, mub, sgw, sgb, alw, alb);
    red_kernel<<<N_SEQ / 8, 256>>>(out);
}

// round 6
// speedup vs baseline: 1.1773x; 1.1773x over previous
#include <cuda_runtime.h>

#define FULLMASK 0xFFFFFFFFu

namespace {
constexpr int N_SEQ = 4096;
constexpr int T = 128;
constexpr float NEG_HALF_LOG2PI = -0.91893853320467274f;
}

__device__ float g_enc[(size_t)N_SEQ * T * 8];
__device__ float g_th[(size_t)N_SEQ * T * 32];
__device__ float g_logp[(size_t)N_SEQ * T];
__device__ float g_dummy[32];

typedef unsigned long long u64;

__device__ __forceinline__ u64 pack2(float lo, float hi)
{
    u64 r;
    asm("mov.b64 %0, {%1, %2};" : "=l"(r) : "f"(lo), "f"(hi));
    return r;
}
__device__ __forceinline__ void unpack2(u64 v, float& lo, float& hi)
{
    asm("mov.b64 {%0, %1}, %2;" : "=f"(lo), "=f"(hi) : "l"(v));
}
__device__ __forceinline__ u64 fma2(u64 a, u64 b, u64 c)
{
    u64 d;
    asm("fma.rn.f32x2 %0, %1, %2, %3;" : "=l"(d) : "l"(a), "l"(b), "l"(c));
    return d;
}
__device__ __forceinline__ u64 mul2(u64 a, u64 b)
{
    u64 d;
    asm("mul.rn.f32x2 %0, %1, %2;" : "=l"(d) : "l"(a), "l"(b));
    return d;
}

// ---------------- dummy probe kernel (shifts ncu -s window onto phi_kernel)
__global__ void probe_kernel()
{
    if (threadIdx.x == 0 && blockIdx.x == 0) g_dummy[0] = 1.0f;
}

// ---------------- encoder: g_enc[n][t][d] = tanh(relu(x*w1+b1) @ w2 + b2)
__global__ void enc_kernel(const float* __restrict__ x,
                           const float* __restrict__ e1w, const float* __restrict__ e1b,
                           const float* __restrict__ e2w, const float* __restrict__ e2b)
{
    __shared__ float s1w[64], s1b[64], s2w[64 * 8], s2b[8];
    int tid = threadIdx.x;
    if (tid < 64) { s1w[tid] = e1w[tid]; s1b[tid] = e1b[tid]; }
    if (tid < 8) s2b[tid] = e2b[tid];
    for (int i = tid; i < 64 * 8; i += blockDim.x) s2w[i] = e2w[i];
    __syncthreads();
    int idx = blockIdx.x * blockDim.x + tid;
    if (idx >= N_SEQ * T) return;
    float xv = x[idx];
    float acc[8];
#pragma unroll
    for (int d = 0; d < 8; d++) acc[d] = s2b[d];
#pragma unroll 8
    for (int h = 0; h < 64; h++) {
        float e = fmaxf(fmaf(xv, s1w[h], s1b[h]), 0.f);
#pragma unroll
        for (int d = 0; d < 8; d++) acc[d] = fmaf(e, s2w[h * 8 + d], acc[d]);
    }
    float4 o0 = make_float4(tanhf(acc[0]), tanhf(acc[1]), tanhf(acc[2]), tanhf(acc[3]));
    float4 o1 = make_float4(tanhf(acc[4]), tanhf(acc[5]), tanhf(acc[6]), tanhf(acc[7]));
    float4* op = reinterpret_cast<float4*>(g_enc + (size_t)idx * 8);
    op[0] = o0;
    op[1] = o1;
}

// ---------------- recurrence (R3 design + e-prefetch): 2-warp pair, 4 seqs,
// i-contraction split across the pair, shuffle broadcast of tmp, ONE named
// 64-thread barrier per step, parity double-buffered partials.
// Block = 128 threads = 2 pairs = 8 sequences. Grid = 512.
__global__ void __launch_bounds__(128) rec_kernel(const float* __restrict__ A,
                                                  const float* __restrict__ initw)
{
    __shared__ ulonglong2 A4[2048];      // [(i*2+q)*32 + L]
    __shared__ float part[2][4][4][32];  // [parity][warpInBlock][seq][lane]
    __shared__ float in_s[32];

    int tid = threadIdx.x;
    for (int idx = tid; idx < 2048; idx += 128) {
        int i = idx >> 6, q = (idx >> 5) & 1, L = idx & 31;
        const float* base = A + i * 256 + q * 128 + L;
        ulonglong2 v;
        v.x = pack2(base[0], base[32]);
        v.y = pack2(base[64], base[96]);
        A4[idx] = v;
    }
    if (tid < 32) in_s[tid] = initw[tid];
    __syncthreads();

    int wib = tid >> 5;          // 0..3 warp in block
    int pairIB = wib >> 1;       // 0..1
    int half = wib & 1;          // which i half
    int L = tid & 31;
    int pairG = blockIdx.x * 2 + pairIB;
    int n0 = pairG * 4;
    int barId = 1 + pairIB;

    float tmp[4];
    float init = in_s[L];
#pragma unroll
    for (int s = 0; s < 4; s++) tmp[s] = init;

    // t = 0 store (this warp's two owned sequences)
    {
        float th0 = tanhf(init);
        int s0 = half * 2;
        g_th[((size_t)(n0 + s0) * T) * 32 + L] = th0;
        g_th[((size_t)(n0 + s0 + 1) * T) * 32 + L] = th0;
    }

    const float4* ep[4];
#pragma unroll
    for (int s = 0; s < 4; s++)
        ep[s] = reinterpret_cast<const float4*>(g_enc + (size_t)(n0 + s) * T * 8);

    int iBase = half * 16;

    // prefetch e for t=1 (index (t-1)*2 = 0)
    float4 ec0[4], ec1[4];
#pragma unroll
    for (int s = 0; s < 4; s++) { ec0[s] = ep[s][0]; ec1[s] = ep[s][1]; }

#pragma unroll 1
    for (int t = 1; t < T; t++) {
        // prefetch next step's e early so LDG latency hides under B-compute
        int tn = (t < T - 1) ? t : T - 2;
        float4 en0[4], en1[4];
#pragma unroll
        for (int s = 0; s < 4; s++) { en0[s] = ep[s][tn * 2]; en1[s] = ep[s][tn * 2 + 1]; }

        u64 B[4][4];
#pragma unroll
        for (int s = 0; s < 4; s++)
#pragma unroll
            for (int k = 0; k < 4; k++) B[s][k] = 0ull;

#pragma unroll 8
        for (int ii = 0; ii < 16; ii++) {
            int i = iBase + ii;
            ulonglong2 a0 = A4[(i * 2 + 0) * 32 + L];
            ulonglong2 a1 = A4[(i * 2 + 1) * 32 + L];
#pragma unroll
            for (int s = 0; s < 4; s++) {
                float vs = __shfl_sync(FULLMASK, tmp[s], i);
                u64 vv = pack2(vs, vs);
                B[s][0] = fma2(vv, a0.x, B[s][0]);
                B[s][1] = fma2(vv, a0.y, B[s][1]);
                B[s][2] = fma2(vv, a1.x, B[s][2]);
                B[s][3] = fma2(vv, a1.y, B[s][3]);
            }
        }

        int par = t & 1;
#pragma unroll
        for (int s = 0; s < 4; s++) {
            u64 acc = mul2(pack2(ec0[s].x, ec0[s].y), B[s][0]);
            acc = fma2(pack2(ec0[s].z, ec0[s].w), B[s][1], acc);
            acc = fma2(pack2(ec1[s].x, ec1[s].y), B[s][2], acc);
            acc = fma2(pack2(ec1[s].z, ec1[s].w), B[s][3], acc);
            float lo, hi;
            unpack2(acc, lo, hi);
            part[par][wib][s][L] = lo + hi;
        }

        asm volatile("bar.sync %0, 64;" :: "r"(barId) : "memory");

        int partner = wib ^ 1;
#pragma unroll
        for (int s = 0; s < 4; s++)
            tmp[s] = part[par][wib][s][L] + part[par][partner][s][L];

        // store tanh for the two sequences this warp owns
        int s0 = half * 2;
        g_th[((size_t)(n0 + s0) * T + t) * 32 + L] = tanhf(tmp[s0]);
        g_th[((size_t)(n0 + s0 + 1) * T + t) * 32 + L] = tanhf(tmp[s0 + 1]);

#pragma unroll
        for (int s = 0; s < 4; s++) { ec0[s] = en0[s]; ec1[s] = en1[s]; }
    }
}

// ---------------- phi: one thread per (n,t) item (exact R3 configuration)
__global__ void __launch_bounds__(256) phi_kernel(
    const float* __restrict__ x,
    const float* __restrict__ w1, const float* __restrict__ b1,
    const float* __restrict__ w2, const float* __restrict__ b2,
    const float* __restrict__ muw, const float* __restrict__ mub,
    const float* __restrict__ sgw, const float* __restrict__ sgb,
    const float* __restrict__ alw, const float* __restrict__ alb)
{
    __shared__ float sm[8352];
    int tid = threadIdx.x;

    for (int i = tid; i < 2048; i += 256) sm[i] = w1[i];
    for (int i = tid; i < 4096; i += 256) sm[2048 + i] = w2[i];
    for (int i = tid; i < 2048; i += 256) {
        int k = i >> 5, c = i & 31;
        float v = 0.f;
        if (c < 10) v = muw[k * 10 + c];
        else if (c < 20) v = sgw[k * 10 + (c - 10)];
        else if (c < 30) v = alw[k * 10 + (c - 20)];
        sm[6144 + i] = v;
    }
    if (tid < 64) { sm[8192 + tid] = b1[tid]; sm[8256 + tid] = b2[tid]; }
    if (tid < 32) {
        float v = 0.f;
        if (tid < 10) v = mub[tid];
        else if (tid < 20) v = sgb[tid - 10];
        else if (tid < 30) v = alb[tid - 20];
        sm[8320 + tid] = v;
    }
    __syncthreads();

    const ulonglong2* w1v = reinterpret_cast<const ulonglong2*>(sm);
    const ulonglong2* w2v = reinterpret_cast<const ulonglong2*>(sm + 2048);
    const ulonglong2* whv = reinterpret_cast<const ulonglong2*>(sm + 6144);
    const u64* b1u = reinterpret_cast<const u64*>(sm + 8192);
    const u64* b2u = reinterpret_cast<const u64*>(sm + 8256);
    const u64* hbu = reinterpret_cast<const u64*>(sm + 8320);

    int item = blockIdx.x * 256 + tid;
    const float4* thp = reinterpret_cast<const float4*>(g_th + (size_t)item * 32);

    u64 hp[32];
#pragma unroll
    for (int p = 0; p < 32; p++) hp[p] = b1u[p];

#pragma unroll
    for (int g = 0; g < 8; g++) {
        float4 v4 = thp[g];
        u64 vv0 = pack2(v4.x, v4.x), vv1 = pack2(v4.y, v4.y);
        u64 vv2 = pack2(v4.z, v4.z), vv3 = pack2(v4.w, v4.w);
#pragma unroll
        for (int q = 0; q < 16; q++) {
            ulonglong2 wA = w1v[(g * 4 + 0) * 16 + q];
            hp[2 * q]     = fma2(vv0, wA.x, hp[2 * q]);
            hp[2 * q + 1] = fma2(vv0, wA.y, hp[2 * q + 1]);
            ulonglong2 wB = w1v[(g * 4 + 1) * 16 + q];
            hp[2 * q]     = fma2(vv1, wB.x, hp[2 * q]);
            hp[2 * q + 1] = fma2(vv1, wB.y, hp[2 * q + 1]);
            ulonglong2 wC = w1v[(g * 4 + 2) * 16 + q];
            hp[2 * q]     = fma2(vv2, wC.x, hp[2 * q]);
            hp[2 * q + 1] = fma2(vv2, wC.y, hp[2 * q + 1]);
            ulonglong2 wD = w1v[(g * 4 + 3) * 16 + q];
            hp[2 * q]     = fma2(vv3, wD.x, hp[2 * q]);
            hp[2 * q + 1] = fma2(vv3, wD.y, hp[2 * q + 1]);
        }
    }
    float h1f[64];
#pragma unroll
    for (int p = 0; p < 32; p++) unpack2(hp[p], h1f[2 * p], h1f[2 * p + 1]);

    u64 h2[32];
#pragma unroll
    for (int p = 0; p < 32; p++) h2[p] = b2u[p];
#pragma unroll
    for (int i = 0; i < 64; i++) {
        float r = fmaxf(h1f[i], 0.f);
        u64 vv = pack2(r, r);
#pragma unroll
        for (int q = 0; q < 16; q++) {
            ulonglong2 w = w2v[i * 16 + q];
            h2[2 * q]     = fma2(vv, w.x, h2[2 * q]);
            h2[2 * q + 1] = fma2(vv, w.y, h2[2 * q + 1]);
        }
    }
    float h2f[64];
#pragma unroll
    for (int p = 0; p < 32; p++) unpack2(h2[p], h2f[2 * p], h2f[2 * p + 1]);

    u64 op[16];
#pragma unroll
    for (int p = 0; p < 16; p++) op[p] = hbu[p];
#pragma unroll
    for (int k = 0; k < 64; k++) {
        float r = fmaxf(h2f[k], 0.f);
        u64 vv = pack2(r, r);
#pragma unroll
        for (int q = 0; q < 8; q++) {
            ulonglong2 w = whv[k * 8 + q];
            op[2 * q]     = fma2(vv, w.x, op[2 * q]);
            op[2 * q + 1] = fma2(vv, w.y, op[2 * q + 1]);
        }
    }

    float o[32];
#pragma unroll
    for (int p = 0; p < 16; p++) unpack2(op[p], o[2 * p], o[2 * p + 1]);

    float xv = x[item];
    float amax = o[20];
#pragma unroll
    for (int k = 1; k < 10; k++) amax = fmaxf(amax, o[20 + k]);
    float asum = 0.f;
#pragma unroll
    for (int k = 0; k < 10; k++) asum += __expf(o[20 + k] - amax);
    float lc = amax + __logf(asum);

    float comp[10];
    float cmax = -1e30f;
#pragma unroll
    for (int k = 0; k < 10; k++) {
        float ls = o[10 + k];
        float z = (xv - o[k]) * __expf(-ls);
        comp[k] = o[20 + k] - lc - ls + NEG_HALF_LOG2PI - 0.5f * z * z;
        cmax = fmaxf(cmax, comp[k]);
    }
    float csum = 0.f;
#pragma unroll
    for (int k = 0; k < 10; k++) csum += __expf(comp[k] - cmax);
    g_logp[item] = cmax + __logf(csum);
}

// ---------------- reduce: out[n] = exp(sum_t logp[n,t]); warp per n
__global__ void __launch_bounds__(256) red_kernel(float* __restrict__ out)
{
    int wid = threadIdx.x >> 5;
    int L = threadIdx.x & 31;
    int n = blockIdx.x * 8 + wid;
    const float* lp = g_logp + (size_t)n * T;
    float s = lp[L] + lp[L + 32] + lp[L + 64] + lp[L + 96];
#pragma unroll
    for (int o = 16; o > 0; o >>= 1) s += __shfl_xor_sync(FULLMASK, s, o);
    if (L == 0) out[n] = __expf(s);
}

extern "C" void kernel_launch(void* const* d_in, const int* in_sizes, int n_in,
                              void* d_out, int out_size)
{
    (void)in_sizes; (void)n_in; (void)out_size;
    const float* x   = (const float*)d_in[0];
    const float* e1w = (const float*)d_in[1];
    const float* e1b = (const float*)d_in[2];
    const float* e2w = (const float*)d_in[3];
    const float* e2b = (const float*)d_in[4];
    const float* A   = (const float*)d_in[5];
    const float* iw  = (const float*)d_in[6];
    const float* w1  = (const float*)d_in[7];
    const float* b1  = (const float*)d_in[8];
    const float* w2  = (const float*)d_in[9];
    const float* b2  = (const float*)d_in[10];
    const float* muw = (const float*)d_in[11];
    const float* mub = (const float*)d_in[12];
    const float* sgw = (const float*)d_in[13];
    const float* sgb = (const float*)d_in[14];
    const float* alw = (const float*)d_in[15];
    const float* alb = (const float*)d_in[16];
    float* out = (float*)d_out;

    probe_kernel<<<1, 32>>>();
    enc_kernel<<<(N_SEQ * T + 255) / 256, 256>>>(x, e1w, e1b, e2w, e2b);
    rec_kernel<<<512, 128>>>(A, iw);
    phi_kernel<<<(N_SEQ * T) / 256, 256>>>(
        x, w1, b1, w2, b2, muw, mub, sgw, sgb, alw, alb);
    red_kernel<<<N_SEQ / 8, 256>>>(out);
}